// round 1
// baseline (speedup 1.0000x reference)
#include <cuda_runtime.h>

// Problem constants (fixed by the reference)
#define N_VOX   1024
#define NUM_RAYS 2048
#define N_SH    9
#define NS      8
#define THREADS 256
#define EARLY_STOP_T 0.01f
#define FAR_PLANE 100.0f

__global__ void __launch_bounds__(THREADS, 1)
voxel_raster_kernel(const float* __restrict__ positions,   // [N,3]
                    const float* __restrict__ sizes,       // [N]
                    const float* __restrict__ densities,   // [N]
                    const float* __restrict__ colors,      // [N, 3*9]
                    const float* __restrict__ ray_o,       // [B,3]
                    const float* __restrict__ ray_d,       // [B,3]
                    float* __restrict__ out)               // rgb[B*3] | depth[B] | weight[B]
{
    const int b = blockIdx.x;

    __shared__ int   s_cnt;
    __shared__ float s_tn[N_VOX];
    __shared__ int   s_id[N_VOX];
    __shared__ float s_ws[N_VOX];
    __shared__ float s_dp[N_VOX];
    __shared__ float s_cr[N_VOX];
    __shared__ float s_cg[N_VOX];
    __shared__ float s_cb[N_VOX];

    if (threadIdx.x == 0) s_cnt = 0;
    __syncthreads();

    const float ox = ray_o[b * 3 + 0];
    const float oy = ray_o[b * 3 + 1];
    const float oz = ray_o[b * 3 + 2];
    const float dx = ray_d[b * 3 + 0];
    const float dy = ray_d[b * 3 + 1];
    const float dz = ray_d[b * 3 + 2];
    const float ix = 1.0f / dx;
    const float iy = 1.0f / dy;
    const float iz = 1.0f / dz;

    // Real SH degree-2 basis in reference order: [1, y, z, x, xy, yz, 3z^2-1, xz, x^2-y^2]
    float sh[N_SH];
    sh[0] = 1.0f;
    sh[1] = dy;
    sh[2] = dz;
    sh[3] = dx;
    sh[4] = dx * dy;
    sh[5] = dy * dz;
    sh[6] = 3.0f * dz * dz - 1.0f;
    sh[7] = dx * dz;
    sh[8] = dx * dx - dy * dy;

    // -------- Phase 1: parallel AABB test; compute full payload for valid hits --------
    for (int v = threadIdx.x; v < N_VOX; v += THREADS) {
        const float px = positions[v * 3 + 0];
        const float py = positions[v * 3 + 1];
        const float pz = positions[v * 3 + 2];
        const float h  = 0.5f * sizes[v];

        const float t0x = (px - h - ox) * ix;
        const float t1x = (px + h - ox) * ix;
        const float t0y = (py - h - oy) * iy;
        const float t1y = (py + h - oy) * iy;
        const float t0z = (pz - h - oz) * iz;
        const float t1z = (pz + h - oz) * iz;

        const float tn = fmaxf(fmaxf(fminf(t0x, t1x), fminf(t0y, t1y)), fminf(t0z, t1z));
        const float tf = fminf(fminf(fmaxf(t0x, t1x), fmaxf(t0y, t1y)), fmaxf(t0z, t1z));

        if (tf > tn && tf > 0.0f) {
            // within-voxel alpha compositing over NS samples (closed per-sample loop)
            const float sigma = expf(densities[v]);
            const float delta = (tf - tn) * (1.0f / (float)NS);
            const float alpha = 1.0f - expf(-sigma * delta);
            const float base  = 1.0f - alpha + 1e-8f;

            float pw = 1.0f, ws = 0.0f, dp = 0.0f;
            const float span = tf - tn;
            #pragma unroll
            for (int i = 0; i < NS; i++) {
                const float w  = alpha * pw;
                const float ts = tn + span * ((float)i / (float)(NS - 1));
                ws += w;
                dp += w * ts;
                pw *= base;
            }

            // SH color for this (ray, voxel)
            const float* c = colors + v * (3 * N_SH);
            float a0 = 0.0f, a1 = 0.0f, a2 = 0.0f;
            #pragma unroll
            for (int k = 0; k < N_SH; k++) {
                a0 += sh[k] * c[k];
                a1 += sh[k] * c[N_SH + k];
                a2 += sh[k] * c[2 * N_SH + k];
            }
            const float cr = 1.0f / (1.0f + expf(-a0));
            const float cg = 1.0f / (1.0f + expf(-a1));
            const float cb = 1.0f / (1.0f + expf(-a2));

            const int slot = atomicAdd(&s_cnt, 1);
            s_tn[slot] = tn;
            s_id[slot] = v;
            s_ws[slot] = ws;
            s_dp[slot] = dp;
            s_cr[slot] = cr;
            s_cg[slot] = cg;
            s_cb[slot] = cb;
        }
    }
    __syncthreads();

    // -------- Phase 2: sort tiny valid list + sequential composite (thread 0) --------
    if (threadIdx.x == 0) {
        const int n = s_cnt;

        // insertion sort by (tn, voxel index) — stable tie-break matches jnp.argsort
        for (int i = 1; i < n; i++) {
            const float tni = s_tn[i];
            const int   idi = s_id[i];
            const float wsi = s_ws[i];
            const float dpi = s_dp[i];
            const float cri = s_cr[i];
            const float cgi = s_cg[i];
            const float cbi = s_cb[i];
            int j = i - 1;
            while (j >= 0 && (s_tn[j] > tni || (s_tn[j] == tni && s_id[j] > idi))) {
                s_tn[j + 1] = s_tn[j];
                s_id[j + 1] = s_id[j];
                s_ws[j + 1] = s_ws[j];
                s_dp[j + 1] = s_dp[j];
                s_cr[j + 1] = s_cr[j];
                s_cg[j + 1] = s_cg[j];
                s_cb[j + 1] = s_cb[j];
                j--;
            }
            s_tn[j + 1] = tni;
            s_id[j + 1] = idi;
            s_ws[j + 1] = wsi;
            s_dp[j + 1] = dpi;
            s_cr[j + 1] = cri;
            s_cg[j + 1] = cgi;
            s_cb[j + 1] = cbi;
        }

        float T = 1.0f;
        float rA = 0.0f, gA = 0.0f, bA = 0.0f, dA = 0.0f, wA = 0.0f;
        for (int i = 0; i < n; i++) {
            if (T < EARLY_STOP_T) break;     // proc = (T_before >= EARLY_STOP_T)
            const float w = s_ws[i];
            const float contrib = T * w;
            rA += contrib * s_cr[i];
            gA += contrib * s_cg[i];
            bA += contrib * s_cb[i];
            dA += T * s_dp[i];
            wA += contrib;
            T *= (1.0f - w);
        }
        // bg color is (0,0,0) -> no T_final term needed
        const float depth = (n > 0) ? dA : FAR_PLANE;   // has_hit == (n > 0)

        out[b * 3 + 0] = rA;
        out[b * 3 + 1] = gA;
        out[b * 3 + 2] = bA;
        out[NUM_RAYS * 3 + b] = depth;
        out[NUM_RAYS * 4 + b] = wA;
    }
}

extern "C" void kernel_launch(void* const* d_in, const int* in_sizes, int n_in,
                              void* d_out, int out_size) {
    const float* positions = (const float*)d_in[0];
    const float* sizes     = (const float*)d_in[1];
    const float* densities = (const float*)d_in[2];
    const float* colors    = (const float*)d_in[3];
    const float* ray_o     = (const float*)d_in[4];
    const float* ray_d     = (const float*)d_in[5];
    float* out = (float*)d_out;

    voxel_raster_kernel<<<NUM_RAYS, THREADS>>>(positions, sizes, densities, colors,
                                               ray_o, ray_d, out);
}

// round 2
// speedup vs baseline: 1.9762x; 1.9762x over previous
#include <cuda_runtime.h>

#define N_VOX        1024
#define NUM_RAYS     2048
#define N_SH         9
#define NS           8
#define RAYS_PER_CTA 4
#define THREADS      (RAYS_PER_CTA * 32)
#define CAP          128           // max hits kept per ray (est. mean ~10, extreme tail << 128)
#define CHUNKS       (CAP / 32)
#define EARLY_STOP_T 0.01f
#define FAR_PLANE    100.0f

// float -> order-preserving uint32 (ascending float == ascending uint)
__device__ __forceinline__ unsigned f2u(float f) {
    unsigned u = __float_as_uint(f);
    return (u & 0x80000000u) ? ~u : (u | 0x80000000u);
}

__global__ void __launch_bounds__(THREADS)
voxel_raster_kernel(const float* __restrict__ positions,   // [N,3]
                    const float* __restrict__ sizes,       // [N]
                    const float* __restrict__ densities,   // [N]
                    const float* __restrict__ colors,      // [N, 27]
                    const float* __restrict__ ray_o,       // [B,3]
                    const float* __restrict__ ray_d,       // [B,3]
                    float* __restrict__ out)               // rgb[3B] | depth[B] | weight[B]
{
    __shared__ unsigned long long s_keys[RAYS_PER_CTA][CAP];
    __shared__ int s_cnt[RAYS_PER_CTA];

    const int warp = threadIdx.x >> 5;
    const int lane = threadIdx.x & 31;
    const int b = blockIdx.x * RAYS_PER_CTA + warp;

    if (lane == 0) s_cnt[warp] = 0;
    __syncwarp();

    const float ox = ray_o[b * 3 + 0];
    const float oy = ray_o[b * 3 + 1];
    const float oz = ray_o[b * 3 + 2];
    const float dx = ray_d[b * 3 + 0];
    const float dy = ray_d[b * 3 + 1];
    const float dz = ray_d[b * 3 + 2];
    const float ix = 1.0f / dx, iy = 1.0f / dy, iz = 1.0f / dz;
    // bound = (p +- h - o) * inv = fma(p +- h, inv, -o*inv)
    const float nx = -ox * ix, ny = -oy * iy, nz = -oz * iz;

    // ---------------- Phase 1: AABB tests, push sortable keys ----------------
    #pragma unroll 4
    for (int i = 0; i < N_VOX / 32; i++) {
        const int v = i * 32 + lane;
        const float px = positions[v * 3 + 0];
        const float py = positions[v * 3 + 1];
        const float pz = positions[v * 3 + 2];
        const float h  = 0.5f * sizes[v];

        const float t0x = fmaf(px - h, ix, nx), t1x = fmaf(px + h, ix, nx);
        const float t0y = fmaf(py - h, iy, ny), t1y = fmaf(py + h, iy, ny);
        const float t0z = fmaf(pz - h, iz, nz), t1z = fmaf(pz + h, iz, nz);

        const float tn = fmaxf(fmaxf(fminf(t0x, t1x), fminf(t0y, t1y)), fminf(t0z, t1z));
        const float tf = fminf(fminf(fmaxf(t0x, t1x), fmaxf(t0y, t1y)), fmaxf(t0z, t1z));

        if (tf > tn && tf > 0.0f) {
            const int slot = atomicAdd(&s_cnt[warp], 1);
            if (slot < CAP)
                s_keys[warp][slot] = ((unsigned long long)f2u(tn) << 32) | (unsigned)v;
        }
    }
    __syncwarp();
    const int n = min(s_cnt[warp], CAP);

    // ---------------- Phase 2: warp-parallel rank sort (keys are unique) ----------------
    unsigned long long myk[CHUNKS];
    int myr[CHUNKS];
    #pragma unroll
    for (int c = 0; c < CHUNKS; c++) {
        const int e = c * 32 + lane;
        myr[c] = -1;
        if (e < n) {
            const unsigned long long k = s_keys[warp][e];
            int r = 0;
            for (int j = 0; j < n; j++) r += (s_keys[warp][j] < k);
            myk[c] = k;
            myr[c] = r;
        }
    }
    __syncwarp();
    #pragma unroll
    for (int c = 0; c < CHUNKS; c++)
        if (myr[c] >= 0) s_keys[warp][myr[c]] = myk[c];
    __syncwarp();

    // SH degree-2 basis, reference order: [1, y, z, x, xy, yz, 3z^2-1, xz, x^2-y^2]
    float sh[N_SH];
    sh[0] = 1.0f;
    sh[1] = dy;  sh[2] = dz;  sh[3] = dx;
    sh[4] = dx * dy;  sh[5] = dy * dz;
    sh[6] = 3.0f * dz * dz - 1.0f;
    sh[7] = dx * dz;  sh[8] = dx * dx - dy * dy;

    // ---------------- Phase 3: payload recompute (32-wide) + replicated composite ----------------
    float T = 1.0f;
    float rA = 0.0f, gA = 0.0f, bA = 0.0f, dA = 0.0f, wA = 0.0f;
    bool stopped = false;

    for (int base = 0; base < n && !stopped; base += 32) {
        const int e = base + lane;
        float ws = 0.0f, dp = 0.0f, cr = 0.0f, cg = 0.0f, cb = 0.0f;

        if (e < n) {
            const unsigned v = (unsigned)(s_keys[warp][e] & 0xFFFFFFFFu);
            const float px = positions[v * 3 + 0];
            const float py = positions[v * 3 + 1];
            const float pz = positions[v * 3 + 2];
            const float h  = 0.5f * sizes[v];

            const float t0x = fmaf(px - h, ix, nx), t1x = fmaf(px + h, ix, nx);
            const float t0y = fmaf(py - h, iy, ny), t1y = fmaf(py + h, iy, ny);
            const float t0z = fmaf(pz - h, iz, nz), t1z = fmaf(pz + h, iz, nz);
            const float tn = fmaxf(fmaxf(fminf(t0x, t1x), fminf(t0y, t1y)), fminf(t0z, t1z));
            const float tf = fminf(fminf(fmaxf(t0x, t1x), fmaxf(t0y, t1y)), fmaxf(t0z, t1z));

            const float sigma = expf(densities[v]);
            const float span  = tf - tn;
            const float delta = span * (1.0f / (float)NS);
            const float alpha = 1.0f - expf(-sigma * delta);
            const float bse   = 1.0f - alpha + 1e-8f;

            float pw = 1.0f;
            #pragma unroll
            for (int s = 0; s < NS; s++) {
                const float w  = alpha * pw;
                const float ts = tn + span * ((float)s / (float)(NS - 1));
                ws += w;
                dp += w * ts;
                pw *= bse;
            }

            const float* c = colors + v * (3 * N_SH);
            float a0 = 0.0f, a1 = 0.0f, a2 = 0.0f;
            #pragma unroll
            for (int k = 0; k < N_SH; k++) {
                a0 += sh[k] * c[k];
                a1 += sh[k] * c[N_SH + k];
                a2 += sh[k] * c[2 * N_SH + k];
            }
            cr = 1.0f / (1.0f + expf(-a0));
            cg = 1.0f / (1.0f + expf(-a1));
            cb = 1.0f / (1.0f + expf(-a2));
        }

        const int m = min(32, n - base);
        for (int j = 0; j < m; j++) {
            // T is replicated across the warp -> uniform break, all lanes in shfl
            if (T < EARLY_STOP_T) { stopped = true; break; }
            const float wsj = __shfl_sync(0xffffffffu, ws, j);
            const float dpj = __shfl_sync(0xffffffffu, dp, j);
            const float crj = __shfl_sync(0xffffffffu, cr, j);
            const float cgj = __shfl_sync(0xffffffffu, cg, j);
            const float cbj = __shfl_sync(0xffffffffu, cb, j);
            const float contrib = T * wsj;
            rA += contrib * crj;
            gA += contrib * cgj;
            bA += contrib * cbj;
            dA += T * dpj;
            wA += contrib;
            T *= (1.0f - wsj);
        }
    }

    if (lane == 0) {
        out[b * 3 + 0] = rA;
        out[b * 3 + 1] = gA;
        out[b * 3 + 2] = bA;
        out[NUM_RAYS * 3 + b] = (n > 0) ? dA : FAR_PLANE;   // has_hit == (n > 0)
        out[NUM_RAYS * 4 + b] = wA;
    }
}

extern "C" void kernel_launch(void* const* d_in, const int* in_sizes, int n_in,
                              void* d_out, int out_size) {
    const float* positions = (const float*)d_in[0];
    const float* sizes     = (const float*)d_in[1];
    const float* densities = (const float*)d_in[2];
    const float* colors    = (const float*)d_in[3];
    const float* ray_o     = (const float*)d_in[4];
    const float* ray_d     = (const float*)d_in[5];
    float* out = (float*)d_out;

    voxel_raster_kernel<<<NUM_RAYS / RAYS_PER_CTA, THREADS>>>(
        positions, sizes, densities, colors, ray_o, ray_d, out);
}

// round 3
// speedup vs baseline: 1.9821x; 1.0030x over previous
#include <cuda_runtime.h>

#define N_VOX        1024
#define NUM_RAYS     2048
#define N_SH         9
#define NS           8
#define THREADS      128           // 4 warps, all cooperating on ONE ray
#define WARPS        4
#define VOX_PER_WARP (N_VOX / WARPS)   // 256 -> 8 tests per lane
#define CAP          128
#define CHUNKS       (CAP / 32)
#define EARLY_STOP_T 0.01f
#define FAR_PLANE    100.0f
#define FULL         0xffffffffu

// float -> order-preserving uint32 (ascending float == ascending uint)
__device__ __forceinline__ unsigned f2u(float f) {
    unsigned u = __float_as_uint(f);
    return (u & 0x80000000u) ? ~u : (u | 0x80000000u);
}

__global__ void __launch_bounds__(THREADS)
voxel_raster_kernel(const float* __restrict__ positions,   // [N,3]
                    const float* __restrict__ sizes,       // [N]
                    const float* __restrict__ densities,   // [N]
                    const float* __restrict__ colors,      // [N, 27]
                    const float* __restrict__ ray_o,       // [B,3]
                    const float* __restrict__ ray_d,       // [B,3]
                    float* __restrict__ out)               // rgb[3B] | depth[B] | weight[B]
{
    __shared__ unsigned long long s_keys[CAP];
    __shared__ float s_tf_src[CAP];
    __shared__ float s_tf_dst[CAP];
    __shared__ int   s_cnt;

    const int b    = blockIdx.x;
    const int warp = threadIdx.x >> 5;
    const int lane = threadIdx.x & 31;

    if (threadIdx.x == 0) s_cnt = 0;
    __syncthreads();

    const float ox = ray_o[b * 3 + 0];
    const float oy = ray_o[b * 3 + 1];
    const float oz = ray_o[b * 3 + 2];
    const float dx = ray_d[b * 3 + 0];
    const float dy = ray_d[b * 3 + 1];
    const float dz = ray_d[b * 3 + 2];
    const float ix = 1.0f / dx, iy = 1.0f / dy, iz = 1.0f / dz;
    const float nx = -ox * ix, ny = -oy * iy, nz = -oz * iz;

    // ---------------- Phase 1: 4 warps x 8 AABB tests per lane ----------------
    #pragma unroll
    for (int i = 0; i < VOX_PER_WARP / 32; i++) {
        const int v = warp * VOX_PER_WARP + i * 32 + lane;
        const float px = positions[v * 3 + 0];
        const float py = positions[v * 3 + 1];
        const float pz = positions[v * 3 + 2];
        const float h  = 0.5f * sizes[v];

        const float t0x = fmaf(px - h, ix, nx), t1x = fmaf(px + h, ix, nx);
        const float t0y = fmaf(py - h, iy, ny), t1y = fmaf(py + h, iy, ny);
        const float t0z = fmaf(pz - h, iz, nz), t1z = fmaf(pz + h, iz, nz);

        const float tn = fmaxf(fmaxf(fminf(t0x, t1x), fminf(t0y, t1y)), fminf(t0z, t1z));
        const float tf = fminf(fminf(fmaxf(t0x, t1x), fmaxf(t0y, t1y)), fmaxf(t0z, t1z));

        if (tf > tn && tf > 0.0f) {
            const int slot = atomicAdd(&s_cnt, 1);
            if (slot < CAP) {
                s_keys[slot]   = ((unsigned long long)f2u(tn) << 32) | (unsigned)v;
                s_tf_src[slot] = tf;
            }
        }
    }
    __syncthreads();

    // ---------------- Phases 2+3: warp 0 only ----------------
    if (warp != 0) return;

    const int n = min(s_cnt, CAP);

    // ---- rank sort by (tn, voxel idx); keys are unique 64-bit ----
    {
        unsigned long long myk[CHUNKS];
        float mytf[CHUNKS];
        int   myr[CHUNKS];
        #pragma unroll
        for (int c = 0; c < CHUNKS; c++) {
            const int e = c * 32 + lane;
            myr[c] = -1;
            if (e < n) {
                const unsigned long long k = s_keys[e];
                int r = 0;
                for (int j = 0; j < n; j++) r += (s_keys[j] < k);
                myk[c]  = k;
                mytf[c] = s_tf_src[e];
                myr[c]  = r;
            }
        }
        __syncwarp();
        #pragma unroll
        for (int c = 0; c < CHUNKS; c++)
            if (myr[c] >= 0) { s_keys[myr[c]] = myk[c]; s_tf_dst[myr[c]] = mytf[c]; }
        __syncwarp();
    }

    // SH degree-2 basis, reference order: [1, y, z, x, xy, yz, 3z^2-1, xz, x^2-y^2]
    float sh[N_SH];
    sh[0] = 1.0f;
    sh[1] = dy;  sh[2] = dz;  sh[3] = dx;
    sh[4] = dx * dy;  sh[5] = dy * dz;
    sh[6] = 3.0f * dz * dz - 1.0f;
    sh[7] = dx * dz;  sh[8] = dx * dx - dy * dy;

    // ---- warp-parallel composite: prefix-product scan per 32-chunk ----
    float T_carry = 1.0f;                       // T_before of first element in chunk
    float rA = 0.0f, gA = 0.0f, bA = 0.0f, dA = 0.0f, wA = 0.0f;

    for (int base = 0; base < n; base += 32) {
        const int e = base + lane;
        float ws = 0.0f, dp = 0.0f, cr = 0.0f, cg = 0.0f, cb = 0.0f;

        if (e < n) {
            const unsigned long long key = s_keys[e];
            const unsigned v  = (unsigned)(key & 0xFFFFFFFFu);
            unsigned tu = (unsigned)(key >> 32);
            const float tn = __uint_as_float((tu & 0x80000000u) ? (tu & 0x7FFFFFFFu) : ~tu);
            const float tf = s_tf_dst[e];

            const float sigma = expf(densities[v]);
            const float span  = tf - tn;
            const float delta = span * (1.0f / (float)NS);
            const float alpha = 1.0f - expf(-sigma * delta);
            const float bse   = 1.0f - alpha + 1e-8f;

            float pw = 1.0f;
            #pragma unroll
            for (int s = 0; s < NS; s++) {
                const float w  = alpha * pw;
                const float ts = tn + span * ((float)s / (float)(NS - 1));
                ws += w;
                dp += w * ts;
                pw *= bse;
            }

            const float* c = colors + v * (3 * N_SH);
            float a0 = 0.0f, a1 = 0.0f, a2 = 0.0f;
            #pragma unroll
            for (int k = 0; k < N_SH; k++) {
                a0 += sh[k] * c[k];
                a1 += sh[k] * c[N_SH + k];
                a2 += sh[k] * c[2 * N_SH + k];
            }
            cr = 1.0f / (1.0f + expf(-a0));
            cg = 1.0f / (1.0f + expf(-a1));
            cb = 1.0f / (1.0f + expf(-a2));
        }

        // inclusive prefix product of one_m (lanes >= n contribute 1.0)
        float pp = 1.0f - ws;
        #pragma unroll
        for (int off = 1; off < 32; off <<= 1) {
            const float vv = __shfl_up_sync(FULL, pp, off);
            if (lane >= off) pp *= vv;
        }
        // exclusive prefix -> T_before per lane
        float ex = __shfl_up_sync(FULL, pp, 1);
        if (lane == 0) ex = 1.0f;
        const float Tb = T_carry * ex;

        const float procf   = (Tb >= EARLY_STOP_T) ? 1.0f : 0.0f;
        const float contrib = Tb * ws * procf;
        rA += contrib * cr;
        gA += contrib * cg;
        bA += contrib * cb;
        dA += Tb * procf * dp;
        wA += contrib;

        T_carry *= __shfl_sync(FULL, pp, 31);
        if (T_carry < EARLY_STOP_T && base + 32 < n) {
            // T_before monotone non-increasing -> all later proc = 0
            break;
        }
    }

    // warp reductions
    #pragma unroll
    for (int off = 16; off > 0; off >>= 1) {
        rA += __shfl_down_sync(FULL, rA, off);
        gA += __shfl_down_sync(FULL, gA, off);
        bA += __shfl_down_sync(FULL, bA, off);
        dA += __shfl_down_sync(FULL, dA, off);
        wA += __shfl_down_sync(FULL, wA, off);
    }

    if (lane == 0) {
        out[b * 3 + 0] = rA;
        out[b * 3 + 1] = gA;
        out[b * 3 + 2] = bA;
        out[NUM_RAYS * 3 + b] = (n > 0) ? dA : FAR_PLANE;   // has_hit == (n > 0)
        out[NUM_RAYS * 4 + b] = wA;
    }
}

extern "C" void kernel_launch(void* const* d_in, const int* in_sizes, int n_in,
                              void* d_out, int out_size) {
    const float* positions = (const float*)d_in[0];
    const float* sizes     = (const float*)d_in[1];
    const float* densities = (const float*)d_in[2];
    const float* colors    = (const float*)d_in[3];
    const float* ray_o     = (const float*)d_in[4];
    const float* ray_d     = (const float*)d_in[5];
    float* out = (float*)d_out;

    voxel_raster_kernel<<<NUM_RAYS, THREADS>>>(positions, sizes, densities, colors,
                                               ray_o, ray_d, out);
}